// round 11
// baseline (speedup 1.0000x reference)
#include <cuda_runtime.h>

#define Hh 64
#define FF 36
#define Ww 8
#define Ss 200
#define KSTRIDE 68       // fp32 K rows; frag LDS.64 banks (4g+2t): conflict-free
#define MBSTRIDE 68      // MB words per o-row; 68 mod 32 = 4 -> conflict-free LDS.64
#define NTHREADS 512

// smem layout in floats
#define OFF_K    0                        // 208*68 = 14144 (rows 200..207 zeroed)
#define OFF_MB   14144                    // 40*68 = 2720 words (bf16x2 hi/lo pairs)
#define OFF_SC   (OFF_MB + 2720)          // 200
#define OFF_MK   (OFF_SC + 200)           // 200 mask flags
#define OFF_RED  (OFF_MK + 200)           // 512 (8 s-groups x 64 h)
#define OFF_D    (OFF_RED + 512)          // 40 (36..39 zero)
#define OFF_W2   (OFF_D + 40)             // 40 (36..39 zero)
#define OFF_Q    (OFF_W2 + 40)            // 64
#define OFF_MISC (OFF_Q + Hh)             // 4: smax, ssum, b2, prelu_a
#define SMEM_FLOATS (OFF_MISC + 4)        // 17924 floats = 71.7 KB -> 2 CTAs/SM

// 0 = mask is int32 (one word per element), 1 = mask is packed bytes (uint8)
__device__ int g_mask_is_bytes;

__global__ void detect_mask_layout(const unsigned int* __restrict__ m, int nwords) {
    __shared__ int found;
    if (threadIdx.x == 0) found = 0;
    __syncthreads();
    int f = 0;
    for (int i = threadIdx.x; i < nwords; i += blockDim.x)
        f |= (m[i] > 1u);
    if (f) atomicOr(&found, 1);
    __syncthreads();
    if (threadIdx.x == 0) g_mask_is_bytes = found;
}

// pack two floats -> bf16x2 (lo half = f0, hi half = f1), round-to-nearest
__device__ __forceinline__ unsigned cvt_bf16x2(float f1, float f0) {
    unsigned r;
    asm("cvt.rn.bf16x2.f32 %0, %1, %2;" : "=r"(r) : "f"(f1), "f"(f0));
    return r;
}
__device__ __forceinline__ float bf16lo_f32(unsigned v) {
    return __uint_as_float(v << 16);
}
__device__ __forceinline__ float bf16hi_f32(unsigned v) {
    return __uint_as_float(v & 0xFFFF0000u);
}
__device__ __forceinline__ float2 lds_f32x2(unsigned a) {
    float2 v;
    asm volatile("ld.shared.v2.f32 {%0,%1}, [%2];" : "=f"(v.x), "=f"(v.y) : "r"(a));
    return v;
}
__device__ __forceinline__ uint2 lds_u32x2(unsigned a) {
    uint2 v;
    asm volatile("ld.shared.v2.b32 {%0,%1}, [%2];" : "=r"(v.x), "=r"(v.y) : "r"(a));
    return v;
}
__device__ __forceinline__ void sts_u32x2(unsigned a, unsigned x, unsigned y) {
    asm volatile("st.shared.v2.b32 [%0], {%1,%2};" :: "r"(a), "r"(x), "r"(y));
}
__device__ __forceinline__ void mma_bf16(float* c, const unsigned* a,
                                         unsigned b0, unsigned b1) {
    asm volatile(
        "mma.sync.aligned.m16n8k16.row.col.f32.bf16.bf16.f32 "
        "{%0,%1,%2,%3}, {%4,%5,%6,%7}, {%8,%9}, {%0,%1,%2,%3};"
        : "+f"(c[0]), "+f"(c[1]), "+f"(c[2]), "+f"(c[3])
        : "r"(a[0]), "r"(a[1]), "r"(a[2]), "r"(a[3]), "r"(b0), "r"(b1));
}

extern "C" __global__ void __launch_bounds__(NTHREADS, 2)
twb_kernel(const float* __restrict__ query,
           const float* __restrict__ key,
           const float* __restrict__ W1,
           const float* __restrict__ b1,
           const float* __restrict__ prelu_a,
           const float* __restrict__ W2,
           const float* __restrict__ b2,
           const void* __restrict__ mask,
           float* __restrict__ out)
{
    extern __shared__ float sm[];
    const int bw  = blockIdx.x;     // b*W + w
    const int b   = bw >> 3;        // W = 8
    const int tid = threadIdx.x;

    // ---- small loads + padding init + mask prefetch ----
    if (tid < Hh) sm[OFF_Q + tid]  = query[b * Hh + tid];
    if (tid < 40) sm[OFF_W2 + tid] = (tid < FF) ? W2[tid] : 0.f;
    if (tid == 0) { sm[OFF_MISC + 2] = b2[0]; sm[OFF_MISC + 3] = prelu_a[0]; }
    if (tid < Ss) {
        int mk = g_mask_is_bytes
               ? ((const unsigned char*)mask)[(size_t)bw * Ss + tid]
               : ((const int*)mask)[(size_t)bw * Ss + tid];
        sm[OFF_MK + tid] = mk ? 1.f : 0.f;
    }
    // zero K pad rows 200..207
    for (int i = tid; i < 8 * KSTRIDE; i += NTHREADS)
        sm[OFF_K + Ss * KSTRIDE + i] = 0.f;
    __syncthreads();   // q needed by M build below

    // ---- stage K tile (200x64) into smem, stride 68 ----
    {
        const float4* gk = (const float4*)(key + (size_t)bw * Ss * Hh);
        for (int i = tid; i < Ss * Hh / 4; i += NTHREADS) {
            int s = i >> 4, c = i & 15;
            float4 v = gk[i];
            *(float4*)&sm[OFF_K + s * KSTRIDE + c * 4] = v;
        }
    }

    // ---- build M_b as interleaved bf16x2 hi/lo pairs, and d_b ----
    // MB word(o, p): offset o*68 + 2p (+0 hi-pair, +1 lo-pair), p = h/2
    {
        const float* q = &sm[OFF_Q];
        const unsigned mb = (unsigned)__cvta_generic_to_shared(&sm[OFF_MB]);
        for (int idx = tid; idx < 40 * 32; idx += NTHREADS) {
            int o = idx >> 5, p = idx & 31;
            float m0 = 0.f, m1 = 0.f;
            if (o < FF) {
                const float* w = W1 + o * 4 * Hh;
                int h0 = 2 * p, h1 = 2 * p + 1;
                m0 = w[Hh + h0] - w[2 * Hh + h0] + w[3 * Hh + h0] * q[h0];
                m1 = w[Hh + h1] - w[2 * Hh + h1] + w[3 * Hh + h1] * q[h1];
            }
            unsigned hi2 = cvt_bf16x2(m1, m0);
            unsigned lo2 = cvt_bf16x2(m1 - bf16hi_f32(hi2), m0 - bf16lo_f32(hi2));
            sts_u32x2(mb + (unsigned)(o * MBSTRIDE + 2 * p) * 4u, hi2, lo2);
        }
        if (tid < 40) {
            float acc = 0.f;
            if (tid < FF) {
                const float* w = W1 + tid * 4 * Hh;
                acc = b1[tid];
                #pragma unroll 8
                for (int h = 0; h < Hh; h++)
                    acc += (w[h] + w[2 * Hh + h]) * q[h];
            }
            sm[OFF_D + tid] = acc;
        }
    }
    __syncthreads();

    // ==== tensor-core score GEMM: bf16x3 on m16n8k16 ====
    // m = s (13 m16 tiles, one per warp), n = o (5 n8 tiles), k = h (4 k16 steps)
    {
        const int wid  = tid >> 5;
        const int lane = tid & 31;
        const int g    = lane >> 2;   // group row
        const int t2   = lane & 3;    // thread-in-group

        if (wid < 13) {
            const int mb16 = wid * 16;
            const unsigned ksm = (unsigned)__cvta_generic_to_shared(&sm[OFF_K]);
            const unsigned mbs = (unsigned)__cvta_generic_to_shared(&sm[OFF_MB]);

            float acc[5][4];
            #pragma unroll
            for (int nt = 0; nt < 5; nt++)
                #pragma unroll
                for (int j = 0; j < 4; j++) acc[nt][j] = 0.f;

            #pragma unroll
            for (int kt = 0; kt < 4; kt++) {
                // A fragment: K rows, 8 fp32 per thread -> bf16 hi/lo
                // a0:(g, c) a1:(g+8, c) a2:(g, c+8) a3:(g+8, c+8), c = kt*16+2*t2
                unsigned ahi[4], alo[4];
                #pragma unroll
                for (int j = 0; j < 4; j++) {
                    int row = mb16 + g + (j & 1) * 8;
                    int col = kt * 16 + 2 * t2 + (j >> 1) * 8;
                    float2 kp = lds_f32x2(ksm + (unsigned)(row * KSTRIDE + col) * 4u);
                    unsigned hi2 = cvt_bf16x2(kp.y, kp.x);
                    ahi[j] = hi2;
                    alo[j] = cvt_bf16x2(kp.y - bf16hi_f32(hi2),
                                        kp.x - bf16lo_f32(hi2));
                }
                #pragma unroll
                for (int nt = 0; nt < 5; nt++) {
                    int o = nt * 8 + g;
                    int p0 = kt * 8 + t2;            // b0 k-pair
                    uint2 B0 = lds_u32x2(mbs + (unsigned)(o * MBSTRIDE + 2 * p0) * 4u);
                    uint2 B1 = lds_u32x2(mbs + (unsigned)(o * MBSTRIDE + 2 * p0 + 8) * 4u);
                    mma_bf16(acc[nt], ahi, B0.x, B1.x);   // khi * mhi
                    mma_bf16(acc[nt], alo, B0.x, B1.x);   // klo * mhi
                    mma_bf16(acc[nt], ahi, B0.y, B1.y);   // khi * mlo
                }
            }

            // epilogue: h -> PReLU -> W2 dot, reduce over 4-lane group
            const float ap  = sm[OFF_MISC + 3];
            const float bb2 = sm[OFF_MISC + 2];
            float p0 = 0.f, p1 = 0.f;           // rows mb16+g, mb16+g+8
            #pragma unroll
            for (int nt = 0; nt < 5; nt++) {
                #pragma unroll
                for (int j = 0; j < 2; j++) {
                    int o = nt * 8 + 2 * t2 + j;
                    float dv = sm[OFF_D + o], wv = sm[OFF_W2 + o];
                    float h0 = acc[nt][j] + dv;
                    h0 = h0 >= 0.f ? h0 : ap * h0;
                    p0 += wv * h0;
                    float h1 = acc[nt][2 + j] + dv;
                    h1 = h1 >= 0.f ? h1 : ap * h1;
                    p1 += wv * h1;
                }
            }
            p0 += __shfl_xor_sync(0xffffffffu, p0, 1);
            p0 += __shfl_xor_sync(0xffffffffu, p0, 2);
            p1 += __shfl_xor_sync(0xffffffffu, p1, 1);
            p1 += __shfl_xor_sync(0xffffffffu, p1, 2);

            if (t2 == 0) {
                int s0 = mb16 + g, s1 = mb16 + g + 8;
                if (s0 < Ss)
                    sm[OFF_SC + s0] = (sm[OFF_MK + s0] != 0.f) ? -10000.0f
                                                               : (p0 + bb2);
                if (s1 < Ss)
                    sm[OFF_SC + s1] = (sm[OFF_MK + s1] != 0.f) ? -10000.0f
                                                               : (p1 + bb2);
            }
        }
    }
    __syncthreads();

    // ---- softmax over S ----
    if (tid < 32) {
        float m = -3.4e38f;
        for (int i = tid; i < Ss; i += 32) m = fmaxf(m, sm[OFF_SC + i]);
        #pragma unroll
        for (int off = 16; off; off >>= 1)
            m = fmaxf(m, __shfl_xor_sync(0xffffffffu, m, off));
        if (tid == 0) sm[OFF_MISC + 0] = m;
    }
    __syncthreads();
    const float smax = sm[OFF_MISC + 0];
    if (tid < Ss) sm[OFF_SC + tid] = __expf(sm[OFF_SC + tid] - smax);
    __syncthreads();
    if (tid < 32) {
        float sum = 0.f;
        for (int i = tid; i < Ss; i += 32) sum += sm[OFF_SC + i];
        #pragma unroll
        for (int off = 16; off; off >>= 1)
            sum += __shfl_xor_sync(0xffffffffu, sum, off);
        if (tid == 0) sm[OFF_MISC + 1] = sum;
    }
    __syncthreads();
    const float inv = 1.0f / sm[OFF_MISC + 1];

    // ---- weighted sum: out[h] = inv * sum_s e[s]*k[s][h] ----
    {
        int h = tid & 63, g = tid >> 6;   // 8 s-groups x 64 h
        float acc = 0.f;
        for (int s = g; s < Ss; s += 8)
            acc += sm[OFF_SC + s] * sm[OFF_K + s * KSTRIDE + h];
        sm[OFF_RED + g * 64 + h] = acc;
    }
    __syncthreads();
    if (tid < Hh) {
        float v = 0.f;
        #pragma unroll
        for (int g = 0; g < 8; g++) v += sm[OFF_RED + g * 64 + tid];
        out[(size_t)bw * Hh + tid] = v * inv;
    }
}

extern "C" void kernel_launch(void* const* d_in, const int* in_sizes, int n_in,
                              void* d_out, int out_size) {
    const float* query          = (const float*)d_in[0];
    const float* key            = (const float*)d_in[1];
    const float* W1             = (const float*)d_in[2];
    const float* b1             = (const float*)d_in[3];
    const float* prelu_a        = (const float*)d_in[4];
    const float* W2             = (const float*)d_in[5];
    const float* b2             = (const float*)d_in[6];
    const void*  mask           = (const void*)d_in[7];
    float* out = (float*)d_out;

    const int B = in_sizes[0] / Hh;      // 512
    const int grid = B * Ww;             // 4096 CTAs, one per (b,w)
    const int smem_bytes = SMEM_FLOATS * sizeof(float);   // ~71.7 KB

    detect_mask_layout<<<1, 256>>>((const unsigned int*)mask, 1024);

    cudaFuncSetAttribute(twb_kernel,
                         cudaFuncAttributeMaxDynamicSharedMemorySize, smem_bytes);
    twb_kernel<<<grid, NTHREADS, smem_bytes>>>(
        query, key, W1, b1, prelu_a, W2, b2, mask, out);
}

// round 12
// speedup vs baseline: 1.4823x; 1.4823x over previous
#include <cuda_runtime.h>

#define Hh 64
#define FF 36
#define Ww 8
#define Ss 200
#define NBW 4096           // 512*8
#define OPAD 40            // o padded to 40 (rows 36..39 zero)

// ---- scratch (device globals; no allocation) ----
__device__ uint2 g_M[512 * OPAD * 32];     // per b: M[o][hpair] as (bf16x2 hi, bf16x2 lo)
__device__ float g_d[512 * OPAD];          // d_b, zero padded
__device__ float g_scores[NBW * Ss];       // raw scores (pre-mask)

// 0 = mask is int32 (one word per element), 1 = mask is packed bytes (uint8)
__device__ int g_mask_is_bytes;

__global__ void detect_mask_layout(const unsigned int* __restrict__ m, int nwords) {
    __shared__ int found;
    if (threadIdx.x == 0) found = 0;
    __syncthreads();
    int f = 0;
    for (int i = threadIdx.x; i < nwords; i += blockDim.x)
        f |= (m[i] > 1u);
    if (f) atomicOr(&found, 1);
    __syncthreads();
    if (threadIdx.x == 0) g_mask_is_bytes = found;
}

// pack two floats -> bf16x2 (lo half = f0, hi half = f1)
__device__ __forceinline__ unsigned cvt_bf16x2(float f1, float f0) {
    unsigned r;
    asm("cvt.rn.bf16x2.f32 %0, %1, %2;" : "=r"(r) : "f"(f1), "f"(f0));
    return r;
}
__device__ __forceinline__ float bf16lo_f32(unsigned v) {
    return __uint_as_float(v << 16);
}
__device__ __forceinline__ float bf16hi_f32(unsigned v) {
    return __uint_as_float(v & 0xFFFF0000u);
}
__device__ __forceinline__ void mma_bf16(float* c, const unsigned* a,
                                         unsigned b0, unsigned b1) {
    asm volatile(
        "mma.sync.aligned.m16n8k16.row.col.f32.bf16.bf16.f32 "
        "{%0,%1,%2,%3}, {%4,%5,%6,%7}, {%8,%9}, {%0,%1,%2,%3};"
        : "+f"(c[0]), "+f"(c[1]), "+f"(c[2]), "+f"(c[3])
        : "r"(a[0]), "r"(a[1]), "r"(a[2]), "r"(a[3]), "r"(b0), "r"(b1));
}

// ==== K0: per-b M (bf16 hi/lo) and d ====
extern "C" __global__ void __launch_bounds__(256)
k0_build(const float* __restrict__ query,
         const float* __restrict__ W1,
         const float* __restrict__ b1)
{
    const int b = blockIdx.x;
    const int tid = threadIdx.x;
    __shared__ float q[Hh];
    if (tid < Hh) q[tid] = query[b * Hh + tid];
    __syncthreads();

    for (int idx = tid; idx < OPAD * 32; idx += 256) {
        int o = idx >> 5, p = idx & 31;
        float m0 = 0.f, m1 = 0.f;
        if (o < FF) {
            const float* w = W1 + o * 4 * Hh;
            int h0 = 2 * p, h1 = 2 * p + 1;
            m0 = w[Hh + h0] - w[2 * Hh + h0] + w[3 * Hh + h0] * q[h0];
            m1 = w[Hh + h1] - w[2 * Hh + h1] + w[3 * Hh + h1] * q[h1];
        }
        unsigned hi2 = cvt_bf16x2(m1, m0);
        unsigned lo2 = cvt_bf16x2(m1 - bf16hi_f32(hi2), m0 - bf16lo_f32(hi2));
        g_M[b * OPAD * 32 + idx] = make_uint2(hi2, lo2);
    }
    if (tid < OPAD) {
        float acc = 0.f;
        if (tid < FF) {
            const float* w = W1 + tid * 4 * Hh;
            acc = b1[tid];
            #pragma unroll 8
            for (int h = 0; h < Hh; h++)
                acc += (w[h] + w[2 * Hh + h]) * q[h];
        }
        g_d[b * OPAD + tid] = acc;
    }
}

// ==== K1: scores via bf16x3 mma; one warp per (bw, m-tile); no smem/barriers ====
extern "C" __global__ void __launch_bounds__(256)
k1_scores(const float* __restrict__ key,
          const float* __restrict__ W2,
          const float* __restrict__ b2,
          const float* __restrict__ prelu_a)
{
    const int gw   = blockIdx.x * 8 + (threadIdx.x >> 5);  // 0..53247
    const int bw   = gw / 13;
    const int mt   = gw - bw * 13;
    const int lane = threadIdx.x & 31;
    const int g    = lane >> 2;
    const int t2   = lane & 3;
    const int mb   = mt * 16;
    const int b    = bw >> 3;

    const float* kb = key + (size_t)bw * Ss * Hh;

    // A fragments: 16 independent LDG.64 (rows >= 200 zeroed)
    unsigned ahi[4][4], alo[4][4];
    {
        float2 kp[4][4];
        #pragma unroll
        for (int kt = 0; kt < 4; kt++)
            #pragma unroll
            for (int j = 0; j < 4; j++) {
                int row = mb + g + (j & 1) * 8;
                int col = kt * 16 + 2 * t2 + (j >> 1) * 8;
                kp[kt][j] = (row < Ss)
                    ? *(const float2*)(kb + row * Hh + col)
                    : make_float2(0.f, 0.f);
            }
        #pragma unroll
        for (int kt = 0; kt < 4; kt++)
            #pragma unroll
            for (int j = 0; j < 4; j++) {
                unsigned hi2 = cvt_bf16x2(kp[kt][j].y, kp[kt][j].x);
                ahi[kt][j] = hi2;
                alo[kt][j] = cvt_bf16x2(kp[kt][j].y - bf16hi_f32(hi2),
                                        kp[kt][j].x - bf16lo_f32(hi2));
            }
    }

    const uint2* Mb = g_M + (size_t)b * OPAD * 32;
    float acc[5][4];
    #pragma unroll
    for (int nt = 0; nt < 5; nt++)
        #pragma unroll
        for (int j = 0; j < 4; j++) acc[nt][j] = 0.f;

    #pragma unroll
    for (int kt = 0; kt < 4; kt++) {
        #pragma unroll
        for (int nt = 0; nt < 5; nt++) {
            int o = nt * 8 + g;
            int p = kt * 8 + t2;
            uint2 B0 = Mb[o * 32 + p];
            uint2 B1 = Mb[o * 32 + p + 4];
            mma_bf16(acc[nt], ahi[kt], B0.x, B1.x);   // khi*mhi
            mma_bf16(acc[nt], alo[kt], B0.x, B1.x);   // klo*mhi
            mma_bf16(acc[nt], ahi[kt], B0.y, B1.y);   // khi*mlo
        }
    }

    // epilogue: PReLU + W2 dot, 4-lane reduce, store scores
    const float ap  = *prelu_a;
    const float bb2 = *b2;
    const float* db = g_d + b * OPAD;
    float p0 = 0.f, p1 = 0.f;
    #pragma unroll
    for (int nt = 0; nt < 5; nt++) {
        #pragma unroll
        for (int j = 0; j < 2; j++) {
            int o = nt * 8 + 2 * t2 + j;
            float dv = db[o];
            float wv = (o < FF) ? W2[o] : 0.f;
            float h0 = acc[nt][j] + dv;
            h0 = h0 >= 0.f ? h0 : ap * h0;
            p0 += wv * h0;
            float h1 = acc[nt][2 + j] + dv;
            h1 = h1 >= 0.f ? h1 : ap * h1;
            p1 += wv * h1;
        }
    }
    p0 += __shfl_xor_sync(0xffffffffu, p0, 1);
    p0 += __shfl_xor_sync(0xffffffffu, p0, 2);
    p1 += __shfl_xor_sync(0xffffffffu, p1, 1);
    p1 += __shfl_xor_sync(0xffffffffu, p1, 2);

    if (t2 == 0) {
        int s0 = mb + g, s1 = mb + g + 8;
        if (s0 < Ss) g_scores[(size_t)bw * Ss + s0] = p0 + bb2;
        if (s1 < Ss) g_scores[(size_t)bw * Ss + s1] = p1 + bb2;
    }
}

// ==== K2: mask + softmax + weighted sum (bandwidth-bound GEMV) ====
extern "C" __global__ void __launch_bounds__(512)
k2_out(const float* __restrict__ key,
       const void* __restrict__ mask,
       float* __restrict__ out)
{
    __shared__ float e[Ss];
    __shared__ float red[512];
    __shared__ float misc[2];
    const int bw  = blockIdx.x;
    const int tid = threadIdx.x;

    if (tid < Ss) {
        float sc = g_scores[(size_t)bw * Ss + tid];
        int mk = g_mask_is_bytes
               ? ((const unsigned char*)mask)[(size_t)bw * Ss + tid]
               : ((const int*)mask)[(size_t)bw * Ss + tid];
        e[tid] = mk ? -10000.0f : sc;
    }
    __syncthreads();
    if (tid < 32) {
        float m = -3.4e38f;
        for (int i = tid; i < Ss; i += 32) m = fmaxf(m, e[i]);
        #pragma unroll
        for (int off = 16; off; off >>= 1)
            m = fmaxf(m, __shfl_xor_sync(0xffffffffu, m, off));
        if (tid == 0) misc[0] = m;
    }
    __syncthreads();
    const float smax = misc[0];
    if (tid < Ss) e[tid] = __expf(e[tid] - smax);
    __syncthreads();
    if (tid < 32) {
        float sum = 0.f;
        for (int i = tid; i < Ss; i += 32) sum += e[i];
        #pragma unroll
        for (int off = 16; off; off >>= 1)
            sum += __shfl_xor_sync(0xffffffffu, sum, off);
        if (tid == 0) misc[1] = sum;
    }
    __syncthreads();
    const float inv = 1.0f / misc[1];

    // weighted sum: 8 s-groups x 64 h, coalesced 128B per warp per iter
    {
        int h = tid & 63, g = tid >> 6;
        const float* kb = key + (size_t)bw * Ss * Hh;
        float acc = 0.f;
        #pragma unroll 5
        for (int s = g; s < Ss; s += 8)
            acc += e[s] * kb[s * Hh + h];
        red[g * 64 + h] = acc;
    }
    __syncthreads();
    if (tid < Hh) {
        float v = 0.f;
        #pragma unroll
        for (int g = 0; g < 8; g++) v += red[g * 64 + tid];
        out[(size_t)bw * Hh + tid] = v * inv;
    }
}

extern "C" void kernel_launch(void* const* d_in, const int* in_sizes, int n_in,
                              void* d_out, int out_size) {
    const float* query          = (const float*)d_in[0];
    const float* key            = (const float*)d_in[1];
    const float* W1             = (const float*)d_in[2];
    const float* b1             = (const float*)d_in[3];
    const float* prelu_a        = (const float*)d_in[4];
    const float* W2             = (const float*)d_in[5];
    const float* b2             = (const float*)d_in[6];
    const void*  mask           = (const void*)d_in[7];
    float* out = (float*)d_out;

    detect_mask_layout<<<1, 256>>>((const unsigned int*)mask, 1024);
    k0_build<<<512, 256>>>(query, W1, b1);
    k1_scores<<<NBW * 13 / 8, 256>>>(key, W2, b2, prelu_a);   // 6656 CTAs
    k2_out<<<NBW, 512>>>(key, mask, out);
}

// round 13
// speedup vs baseline: 1.8306x; 1.2350x over previous
#include <cuda_runtime.h>

#define Hh 64
#define FF 36
#define Ww 8
#define Ss 200
#define NBW 4096           // 512*8
#define OPAD 40            // o padded to 40 (rows 36..39 zero)
#define MSTR 36            // smem M row stride (words): lane bank = 4g+t2 -> conflict-free

// ---- scratch (device globals; no allocation) ----
__device__ uint2 g_M[512 * OPAD * 32];     // per b: M[o][hpair] as (bf16x2 hi, bf16x2 lo)
__device__ float g_d[512 * OPAD];          // d_b, zero padded
__device__ float g_scores[NBW * Ss];       // raw scores (pre-mask)

// 0 = mask is int32 (one word per element), 1 = mask is packed bytes (uint8)
__device__ int g_mask_is_bytes;

__global__ void detect_mask_layout(const unsigned int* __restrict__ m, int nwords) {
    __shared__ int found;
    if (threadIdx.x == 0) found = 0;
    __syncthreads();
    int f = 0;
    for (int i = threadIdx.x; i < nwords; i += blockDim.x)
        f |= (m[i] > 1u);
    if (f) atomicOr(&found, 1);
    __syncthreads();
    if (threadIdx.x == 0) g_mask_is_bytes = found;
}

// pack two floats -> bf16x2 (lo half = f0, hi half = f1)
__device__ __forceinline__ unsigned cvt_bf16x2(float f1, float f0) {
    unsigned r;
    asm("cvt.rn.bf16x2.f32 %0, %1, %2;" : "=r"(r) : "f"(f1), "f"(f0));
    return r;
}
__device__ __forceinline__ float bf16lo_f32(unsigned v) {
    return __uint_as_float(v << 16);
}
__device__ __forceinline__ float bf16hi_f32(unsigned v) {
    return __uint_as_float(v & 0xFFFF0000u);
}
__device__ __forceinline__ void mma_bf16(float* c, const unsigned* a,
                                         unsigned b0, unsigned b1) {
    asm volatile(
        "mma.sync.aligned.m16n8k16.row.col.f32.bf16.bf16.f32 "
        "{%0,%1,%2,%3}, {%4,%5,%6,%7}, {%8,%9}, {%0,%1,%2,%3};"
        : "+f"(c[0]), "+f"(c[1]), "+f"(c[2]), "+f"(c[3])
        : "r"(a[0]), "r"(a[1]), "r"(a[2]), "r"(a[3]), "r"(b0), "r"(b1));
}

// ==== K0: per-b M (bf16 hi/lo) and d ====
extern "C" __global__ void __launch_bounds__(256)
k0_build(const float* __restrict__ query,
         const float* __restrict__ W1,
         const float* __restrict__ b1)
{
    const int b = blockIdx.x;
    const int tid = threadIdx.x;
    __shared__ float q[Hh];
    if (tid < Hh) q[tid] = query[b * Hh + tid];
    __syncthreads();

    for (int idx = tid; idx < OPAD * 32; idx += 256) {
        int o = idx >> 5, p = idx & 31;
        float m0 = 0.f, m1 = 0.f;
        if (o < FF) {
            const float* w = W1 + o * 4 * Hh;
            int h0 = 2 * p, h1 = 2 * p + 1;
            m0 = w[Hh + h0] - w[2 * Hh + h0] + w[3 * Hh + h0] * q[h0];
            m1 = w[Hh + h1] - w[2 * Hh + h1] + w[3 * Hh + h1] * q[h1];
        }
        unsigned hi2 = cvt_bf16x2(m1, m0);
        unsigned lo2 = cvt_bf16x2(m1 - bf16hi_f32(hi2), m0 - bf16lo_f32(hi2));
        g_M[b * OPAD * 32 + idx] = make_uint2(hi2, lo2);
    }
    if (tid < OPAD) {
        float acc = 0.f;
        if (tid < FF) {
            const float* w = W1 + tid * 4 * Hh;
            acc = b1[tid];
            #pragma unroll 8
            for (int h = 0; h < Hh; h++)
                acc += (w[h] + w[2 * Hh + h]) * q[h];
        }
        g_d[b * OPAD + tid] = acc;
    }
}

// ==== K1: scores; CTA = one bw (13 warps), M staged in smem, B via LDS ====
extern "C" __global__ void __launch_bounds__(416, 2)
k1_scores(const float* __restrict__ key,
          const float* __restrict__ W2,
          const float* __restrict__ b2,
          const float* __restrict__ prelu_a)
{
    __shared__ unsigned Mhi[OPAD * MSTR];
    __shared__ unsigned Mlo[OPAD * MSTR];
    __shared__ float dsm[OPAD], wsm[OPAD], scal[2];

    const int bw  = blockIdx.x;
    const int b   = bw >> 3;
    const int tid = threadIdx.x;

    // stage M (bf16 hi/lo, stride-36 words), d, W2
    for (int idx = tid; idx < OPAD * 32; idx += 416) {
        int o = idx >> 5, p = idx & 31;
        uint2 v = g_M[b * OPAD * 32 + idx];
        Mhi[o * MSTR + p] = v.x;
        Mlo[o * MSTR + p] = v.y;
    }
    if (tid < OPAD) {
        dsm[tid] = g_d[b * OPAD + tid];
        wsm[tid] = (tid < FF) ? W2[tid] : 0.f;
    }
    if (tid == 0) { scal[0] = *prelu_a; scal[1] = *b2; }

    // A fragments while M stages: front-loaded LDG from key
    const int lane = tid & 31;
    const int g    = lane >> 2;
    const int t2   = lane & 3;
    const int mt   = tid >> 5;          // warp = m-tile, 0..12
    const int mb   = mt * 16;
    const float* kb = key + (size_t)bw * Ss * Hh;

    unsigned ahi[4][4], alo[4][4];
    {
        float2 kp[4][4];
        #pragma unroll
        for (int kt = 0; kt < 4; kt++)
            #pragma unroll
            for (int j = 0; j < 4; j++) {
                int row = mb + g + (j & 1) * 8;
                int col = kt * 16 + 2 * t2 + (j >> 1) * 8;
                kp[kt][j] = (row < Ss)
                    ? *(const float2*)(kb + row * Hh + col)
                    : make_float2(0.f, 0.f);
            }
        #pragma unroll
        for (int kt = 0; kt < 4; kt++)
            #pragma unroll
            for (int j = 0; j < 4; j++) {
                unsigned hi2 = cvt_bf16x2(kp[kt][j].y, kp[kt][j].x);
                ahi[kt][j] = hi2;
                alo[kt][j] = cvt_bf16x2(kp[kt][j].y - bf16hi_f32(hi2),
                                        kp[kt][j].x - bf16lo_f32(hi2));
            }
    }
    __syncthreads();

    float acc[5][4];
    #pragma unroll
    for (int nt = 0; nt < 5; nt++)
        #pragma unroll
        for (int j = 0; j < 4; j++) acc[nt][j] = 0.f;

    #pragma unroll
    for (int kt = 0; kt < 4; kt++) {
        #pragma unroll
        for (int nt = 0; nt < 5; nt++) {
            int o = nt * 8 + g;
            int p = kt * 8 + t2;
            unsigned bh0 = Mhi[o * MSTR + p];
            unsigned bh1 = Mhi[o * MSTR + p + 4];
            unsigned bl0 = Mlo[o * MSTR + p];
            unsigned bl1 = Mlo[o * MSTR + p + 4];
            mma_bf16(acc[nt], ahi[kt], bh0, bh1);   // khi*mhi
            mma_bf16(acc[nt], alo[kt], bh0, bh1);   // klo*mhi
            mma_bf16(acc[nt], ahi[kt], bl0, bl1);   // khi*mlo
        }
    }

    // epilogue: PReLU + W2 dot, 4-lane reduce, store scores
    const float ap  = scal[0];
    const float bb2 = scal[1];
    float p0 = 0.f, p1 = 0.f;
    #pragma unroll
    for (int nt = 0; nt < 5; nt++) {
        #pragma unroll
        for (int j = 0; j < 2; j++) {
            int o = nt * 8 + 2 * t2 + j;
            float dv = dsm[o], wv = wsm[o];
            float h0 = acc[nt][j] + dv;
            h0 = h0 >= 0.f ? h0 : ap * h0;
            p0 += wv * h0;
            float h1 = acc[nt][2 + j] + dv;
            h1 = h1 >= 0.f ? h1 : ap * h1;
            p1 += wv * h1;
        }
    }
    p0 += __shfl_xor_sync(0xffffffffu, p0, 1);
    p0 += __shfl_xor_sync(0xffffffffu, p0, 2);
    p1 += __shfl_xor_sync(0xffffffffu, p1, 1);
    p1 += __shfl_xor_sync(0xffffffffu, p1, 2);

    if (t2 == 0) {
        int s0 = mb + g, s1 = mb + g + 8;
        if (s0 < Ss) g_scores[(size_t)bw * Ss + s0] = p0 + bb2;
        if (s1 < Ss) g_scores[(size_t)bw * Ss + s1] = p1 + bb2;
    }
}

// ==== K2: mask + softmax + weighted sum (bandwidth-bound GEMV) ====
extern "C" __global__ void __launch_bounds__(512)
k2_out(const float* __restrict__ key,
       const void* __restrict__ mask,
       float* __restrict__ out)
{
    __shared__ float e[Ss];
    __shared__ float red[512];
    __shared__ float misc[2];
    const int bw  = blockIdx.x;
    const int tid = threadIdx.x;

    if (tid < Ss) {
        float sc = g_scores[(size_t)bw * Ss + tid];
        int mk = g_mask_is_bytes
               ? ((const unsigned char*)mask)[(size_t)bw * Ss + tid]
               : ((const int*)mask)[(size_t)bw * Ss + tid];
        e[tid] = mk ? -10000.0f : sc;
    }
    __syncthreads();
    if (tid < 32) {
        float m = -3.4e38f;
        for (int i = tid; i < Ss; i += 32) m = fmaxf(m, e[i]);
        #pragma unroll
        for (int off = 16; off; off >>= 1)
            m = fmaxf(m, __shfl_xor_sync(0xffffffffu, m, off));
        if (tid == 0) misc[0] = m;
    }
    __syncthreads();
    const float smax = misc[0];
    if (tid < Ss) e[tid] = __expf(e[tid] - smax);
    __syncthreads();
    if (tid < 32) {
        float sum = 0.f;
        for (int i = tid; i < Ss; i += 32) sum += e[i];
        #pragma unroll
        for (int off = 16; off; off >>= 1)
            sum += __shfl_xor_sync(0xffffffffu, sum, off);
        if (tid == 0) misc[1] = sum;
    }
    __syncthreads();
    const float inv = 1.0f / misc[1];

    // weighted sum: 8 s-groups x 64 h, coalesced 128B per warp per iter
    {
        int h = tid & 63, g = tid >> 6;
        const float* kb = key + (size_t)bw * Ss * Hh;
        float acc = 0.f;
        #pragma unroll 5
        for (int s = g; s < Ss; s += 8)
            acc += e[s] * kb[s * Hh + h];
        red[g * 64 + h] = acc;
    }
    __syncthreads();
    if (tid < Hh) {
        float v = 0.f;
        #pragma unroll
        for (int g = 0; g < 8; g++) v += red[g * 64 + tid];
        out[(size_t)bw * Hh + tid] = v * inv;
    }
}

extern "C" void kernel_launch(void* const* d_in, const int* in_sizes, int n_in,
                              void* d_out, int out_size) {
    const float* query          = (const float*)d_in[0];
    const float* key            = (const float*)d_in[1];
    const float* W1             = (const float*)d_in[2];
    const float* b1             = (const float*)d_in[3];
    const float* prelu_a        = (const float*)d_in[4];
    const float* W2             = (const float*)d_in[5];
    const float* b2             = (const float*)d_in[6];
    const void*  mask           = (const void*)d_in[7];
    float* out = (float*)d_out;

    detect_mask_layout<<<1, 256>>>((const unsigned int*)mask, 1024);
    k0_build<<<512, 256>>>(query, W1, b1);
    k1_scores<<<NBW, 416>>>(key, W2, b2, prelu_a);
    k2_out<<<NBW, 512>>>(key, mask, out);
}

// round 14
// speedup vs baseline: 1.8537x; 1.0126x over previous
#include <cuda_runtime.h>

#define Hh 64
#define FF 36
#define Ww 8
#define Ss 200
#define NBW 4096           // 512*8
#define OPAD 40            // o padded to 40 (rows 36..39 zero)
#define MSTR 36            // smem M row stride (words): lane bank = 4g+t2 -> conflict-free
#define KSTR 68            // smem K row stride (floats)

// ---- scratch (device globals; no allocation) ----
__device__ uint2 g_M[512 * OPAD * 32];     // per b: M[o][hpair] as (bf16x2 hi, bf16x2 lo)
__device__ float g_d[512 * OPAD];          // d_b, zero padded

// 0 = mask is int32 (one word per element), 1 = mask is packed bytes (uint8)
__device__ int g_mask_is_bytes;

__global__ void detect_mask_layout(const unsigned int* __restrict__ m, int nwords) {
    __shared__ int found;
    if (threadIdx.x == 0) found = 0;
    __syncthreads();
    int f = 0;
    for (int i = threadIdx.x; i < nwords; i += blockDim.x)
        f |= (m[i] > 1u);
    if (f) atomicOr(&found, 1);
    __syncthreads();
    if (threadIdx.x == 0) g_mask_is_bytes = found;
}

// pack two floats -> bf16x2 (lo half = f0, hi half = f1)
__device__ __forceinline__ unsigned cvt_bf16x2(float f1, float f0) {
    unsigned r;
    asm("cvt.rn.bf16x2.f32 %0, %1, %2;" : "=r"(r) : "f"(f1), "f"(f0));
    return r;
}
__device__ __forceinline__ float bf16lo_f32(unsigned v) {
    return __uint_as_float(v << 16);
}
__device__ __forceinline__ float bf16hi_f32(unsigned v) {
    return __uint_as_float(v & 0xFFFF0000u);
}
__device__ __forceinline__ void mma_bf16(float* c, const unsigned* a,
                                         unsigned b0, unsigned b1) {
    asm volatile(
        "mma.sync.aligned.m16n8k16.row.col.f32.bf16.bf16.f32 "
        "{%0,%1,%2,%3}, {%4,%5,%6,%7}, {%8,%9}, {%0,%1,%2,%3};"
        : "+f"(c[0]), "+f"(c[1]), "+f"(c[2]), "+f"(c[3])
        : "r"(a[0]), "r"(a[1]), "r"(a[2]), "r"(a[3]), "r"(b0), "r"(b1));
}

// ==== K0: per-b M (bf16 hi/lo) and d ====
extern "C" __global__ void __launch_bounds__(256)
k0_build(const float* __restrict__ query,
         const float* __restrict__ W1,
         const float* __restrict__ b1)
{
    const int b = blockIdx.x;
    const int tid = threadIdx.x;
    __shared__ float q[Hh];
    if (tid < Hh) q[tid] = query[b * Hh + tid];
    __syncthreads();

    for (int idx = tid; idx < OPAD * 32; idx += 256) {
        int o = idx >> 5, p = idx & 31;
        float m0 = 0.f, m1 = 0.f;
        if (o < FF) {
            const float* w = W1 + o * 4 * Hh;
            int h0 = 2 * p, h1 = 2 * p + 1;
            m0 = w[Hh + h0] - w[2 * Hh + h0] + w[3 * Hh + h0] * q[h0];
            m1 = w[Hh + h1] - w[2 * Hh + h1] + w[3 * Hh + h1] * q[h1];
        }
        unsigned hi2 = cvt_bf16x2(m1, m0);
        unsigned lo2 = cvt_bf16x2(m1 - bf16hi_f32(hi2), m0 - bf16lo_f32(hi2));
        g_M[b * OPAD * 32 + idx] = make_uint2(hi2, lo2);
    }
    if (tid < OPAD) {
        float acc = 0.f;
        if (tid < FF) {
            const float* w = W1 + tid * 4 * Hh;
            acc = b1[tid];
            #pragma unroll 8
            for (int h = 0; h < Hh; h++)
                acc += (w[h] + w[2 * Hh + h]) * q[h];
        }
        g_d[b * OPAD + tid] = acc;
    }
}

// ==== K1 fused: scores (bf16x3 mma) + softmax + weighted sum; key read ONCE ====
extern "C" __global__ void __launch_bounds__(416, 2)
k1_fused(const float* __restrict__ key,
         const float* __restrict__ W2,
         const float* __restrict__ b2,
         const float* __restrict__ prelu_a,
         const void* __restrict__ mask,
         float* __restrict__ out)
{
    __shared__ float Ksm[Ss * KSTR];           // 54.4 KB, fp32 K tile
    __shared__ unsigned Mhi[OPAD * MSTR];
    __shared__ unsigned Mlo[OPAD * MSTR];
    __shared__ float e[Ss];
    __shared__ float red[384];
    __shared__ float dsm[OPAD], wsm[OPAD], scal[2], misc[2];
    __shared__ float mkf[Ss];

    const int bw  = blockIdx.x;
    const int b   = bw >> 3;
    const int tid = threadIdx.x;

    // stage M (bf16 hi/lo), d, W2, scalars, mask flags
    for (int idx = tid; idx < OPAD * 32; idx += 416) {
        int o = idx >> 5, p = idx & 31;
        uint2 v = g_M[b * OPAD * 32 + idx];
        Mhi[o * MSTR + p] = v.x;
        Mlo[o * MSTR + p] = v.y;
    }
    if (tid < OPAD) {
        dsm[tid] = g_d[b * OPAD + tid];
        wsm[tid] = (tid < FF) ? W2[tid] : 0.f;
    }
    if (tid == 0) { scal[0] = *prelu_a; scal[1] = *b2; }
    if (tid < Ss) {
        int mk = g_mask_is_bytes
               ? ((const unsigned char*)mask)[(size_t)bw * Ss + tid]
               : ((const int*)mask)[(size_t)bw * Ss + tid];
        mkf[tid] = mk ? 1.f : 0.f;
    }

    const int lane = tid & 31;
    const int g    = lane >> 2;
    const int t2   = lane & 3;
    const int mt   = tid >> 5;          // warp = m-tile, 0..12
    const int mb   = mt * 16;
    const float* kb = key + (size_t)bw * Ss * Hh;

    // A fragments: front-loaded 16 LDG.64 from key (the ONLY key DRAM read),
    // stored to smem K tile for the weighted-sum epilogue, then cvt to bf16 hi/lo.
    unsigned ahi[4][4], alo[4][4];
    {
        float2 kp[4][4];
        #pragma unroll
        for (int kt = 0; kt < 4; kt++)
            #pragma unroll
            for (int j = 0; j < 4; j++) {
                int row = mb + g + (j & 1) * 8;
                int col = kt * 16 + 2 * t2 + (j >> 1) * 8;
                kp[kt][j] = (row < Ss)
                    ? *(const float2*)(kb + row * Hh + col)
                    : make_float2(0.f, 0.f);
            }
        #pragma unroll
        for (int kt = 0; kt < 4; kt++)
            #pragma unroll
            for (int j = 0; j < 4; j++) {
                int row = mb + g + (j & 1) * 8;
                int col = kt * 16 + 2 * t2 + (j >> 1) * 8;
                if (row < Ss)
                    *(float2*)&Ksm[row * KSTR + col] = kp[kt][j];
                unsigned hi2 = cvt_bf16x2(kp[kt][j].y, kp[kt][j].x);
                ahi[kt][j] = hi2;
                alo[kt][j] = cvt_bf16x2(kp[kt][j].y - bf16hi_f32(hi2),
                                        kp[kt][j].x - bf16lo_f32(hi2));
            }
    }
    __syncthreads();

    float acc[5][4];
    #pragma unroll
    for (int nt = 0; nt < 5; nt++)
        #pragma unroll
        for (int j = 0; j < 4; j++) acc[nt][j] = 0.f;

    #pragma unroll
    for (int kt = 0; kt < 4; kt++) {
        #pragma unroll
        for (int nt = 0; nt < 5; nt++) {
            int o = nt * 8 + g;
            int p = kt * 8 + t2;
            unsigned bh0 = Mhi[o * MSTR + p];
            unsigned bh1 = Mhi[o * MSTR + p + 4];
            unsigned bl0 = Mlo[o * MSTR + p];
            unsigned bl1 = Mlo[o * MSTR + p + 4];
            mma_bf16(acc[nt], ahi[kt], bh0, bh1);   // khi*mhi
            mma_bf16(acc[nt], alo[kt], bh0, bh1);   // klo*mhi
            mma_bf16(acc[nt], ahi[kt], bl0, bl1);   // khi*mlo
        }
    }

    // score epilogue: PReLU + W2 dot, 4-lane reduce, mask, write e[]
    {
        const float ap  = scal[0];
        const float bb2 = scal[1];
        float p0 = 0.f, p1 = 0.f;
        #pragma unroll
        for (int nt = 0; nt < 5; nt++) {
            #pragma unroll
            for (int j = 0; j < 2; j++) {
                int o = nt * 8 + 2 * t2 + j;
                float dv = dsm[o], wv = wsm[o];
                float h0 = acc[nt][j] + dv;
                h0 = h0 >= 0.f ? h0 : ap * h0;
                p0 += wv * h0;
                float h1 = acc[nt][2 + j] + dv;
                h1 = h1 >= 0.f ? h1 : ap * h1;
                p1 += wv * h1;
            }
        }
        p0 += __shfl_xor_sync(0xffffffffu, p0, 1);
        p0 += __shfl_xor_sync(0xffffffffu, p0, 2);
        p1 += __shfl_xor_sync(0xffffffffu, p1, 1);
        p1 += __shfl_xor_sync(0xffffffffu, p1, 2);

        if (t2 == 0) {
            int s0 = mb + g, s1 = mb + g + 8;
            if (s0 < Ss) e[s0] = (mkf[s0] != 0.f) ? -10000.0f : (p0 + bb2);
            if (s1 < Ss) e[s1] = (mkf[s1] != 0.f) ? -10000.0f : (p1 + bb2);
        }
    }
    __syncthreads();

    // softmax over S
    if (tid < 32) {
        float m = -3.4e38f;
        for (int i = tid; i < Ss; i += 32) m = fmaxf(m, e[i]);
        #pragma unroll
        for (int off = 16; off; off >>= 1)
            m = fmaxf(m, __shfl_xor_sync(0xffffffffu, m, off));
        if (tid == 0) misc[0] = m;
    }
    __syncthreads();
    const float smax = misc[0];
    if (tid < Ss) e[tid] = __expf(e[tid] - smax);
    __syncthreads();
    if (tid < 32) {
        float sum = 0.f;
        for (int i = tid; i < Ss; i += 32) sum += e[i];
        #pragma unroll
        for (int off = 16; off; off >>= 1)
            sum += __shfl_xor_sync(0xffffffffu, sum, off);
        if (tid == 0) misc[1] = sum;
    }
    __syncthreads();
    const float inv = 1.0f / misc[1];

    // weighted sum from smem K: 6 s-groups x 64 h (384 threads)
    if (tid < 384) {
        int h = tid & 63, sg = tid >> 6;
        float acc2 = 0.f;
        for (int s = sg; s < Ss; s += 6)
            acc2 += e[s] * Ksm[s * KSTR + h];
        red[sg * 64 + h] = acc2;
    }
    __syncthreads();
    if (tid < Hh) {
        float v = 0.f;
        #pragma unroll
        for (int sg = 0; sg < 6; sg++) v += red[sg * 64 + tid];
        out[(size_t)bw * Hh + tid] = v * inv;
    }
}

extern "C" void kernel_launch(void* const* d_in, const int* in_sizes, int n_in,
                              void* d_out, int out_size) {
    const float* query          = (const float*)d_in[0];
    const float* key            = (const float*)d_in[1];
    const float* W1             = (const float*)d_in[2];
    const float* b1             = (const float*)d_in[3];
    const float* prelu_a        = (const float*)d_in[4];
    const float* W2             = (const float*)d_in[5];
    const float* b2             = (const float*)d_in[6];
    const void*  mask           = (const void*)d_in[7];
    float* out = (float*)d_out;

    detect_mask_layout<<<1, 256>>>((const unsigned int*)mask, 1024);
    k0_build<<<512, 256>>>(query, W1, b1);
    k1_fused<<<NBW, 416>>>(key, W2, b2, prelu_a, mask, out);
}